// round 2
// baseline (speedup 1.0000x reference)
#include <cuda_runtime.h>
#include <cuda_bf16.h>
#include <math.h>

// Problem constants (B=1, L=4096, DM=1024, NH=16, DH=64, w=512, C=8)
#define L_TOK   4096
#define DMODEL  1024
#define NHEAD   16
#define DHEAD   64
#define WCHUNK  512
#define NCHUNK  8
#define NKEY    (3 * WCHUNK)        // 1536 effective keys
#define NQROW   (L_TOK * NHEAD)     // 65536 query rows of dim 64

// -------------------- scratch (no cudaMalloc allowed) --------------------
__device__ float g_qp [L_TOK * DMODEL];       // 16 MB
__device__ float g_kvp[L_TOK * 2 * DHEAD];    // 2 MB
__device__ float g_keff[NKEY * DHEAD];        // 384 KB
__device__ float g_veff[NKEY * DHEAD];        // 384 KB
__device__ float g_ctx[L_TOK * DMODEL];       // 16 MB

// -------------------- generic tiled SGEMM: C = alpha * A(MxK) * B(KxN) ----
// BM=BN=128, BK=8, 256 threads, 8x8 microtile. M,N,K multiples of tiles.
__global__ __launch_bounds__(256) void sgemm128(
    const float* __restrict__ A, const float* __restrict__ B,
    float* __restrict__ C, int M, int N, int K, float alpha)
{
    __shared__ float As[8][128];
    __shared__ float Bs[8][128];

    const int tid = threadIdx.x;
    const int bm = blockIdx.y * 128;
    const int bn = blockIdx.x * 128;
    const int tr = tid >> 4;          // 0..15
    const int tc = tid & 15;          // 0..15

    // A loader: thread -> (row = tid/2, kcol = (tid&1)*4), float4 along K
    const int arow = tid >> 1;
    const int acol = (tid & 1) * 4;
    // B loader: thread -> (krow = tid/32, col = (tid&31)*4), float4 along N
    const int brow = tid >> 5;
    const int bcol = (tid & 31) * 4;

    const float* Aptr = A + (size_t)(bm + arow) * K + acol;
    const float* Bptr = B + (size_t)brow * N + bn + bcol;

    float acc[8][8];
#pragma unroll
    for (int i = 0; i < 8; i++)
#pragma unroll
        for (int j = 0; j < 8; j++) acc[i][j] = 0.f;

    for (int k0 = 0; k0 < K; k0 += 8) {
        float4 av = *(const float4*)(Aptr + k0);
        float4 bv = *(const float4*)(Bptr + (size_t)k0 * N);
        __syncthreads();                 // previous tile's compute done
        As[acol + 0][arow] = av.x;
        As[acol + 1][arow] = av.y;
        As[acol + 2][arow] = av.z;
        As[acol + 3][arow] = av.w;
        *(float4*)&Bs[brow][bcol] = bv;
        __syncthreads();

#pragma unroll
        for (int kk = 0; kk < 8; ++kk) {
            float a[8], b[8];
            *(float4*)(a)     = *(const float4*)&As[kk][tr * 8];
            *(float4*)(a + 4) = *(const float4*)&As[kk][tr * 8 + 4];
            *(float4*)(b)     = *(const float4*)&Bs[kk][tc * 8];
            *(float4*)(b + 4) = *(const float4*)&Bs[kk][tc * 8 + 4];
#pragma unroll
            for (int i = 0; i < 8; i++)
#pragma unroll
                for (int j = 0; j < 8; j++)
                    acc[i][j] += a[i] * b[j];
        }
    }

#pragma unroll
    for (int i = 0; i < 8; i++) {
        float* crow = C + (size_t)(bm + tr * 8 + i) * N + bn + tc * 8;
#pragma unroll
        for (int j4 = 0; j4 < 2; j4++) {
            float4 v;
            v.x = alpha * acc[i][j4 * 4 + 0];
            v.y = alpha * acc[i][j4 * 4 + 1];
            v.z = alpha * acc[i][j4 * 4 + 2];
            v.w = alpha * acc[i][j4 * 4 + 3];
            *(float4*)(crow + j4 * 4) = v;
        }
    }
}

// -------------------- build K_eff / V_eff from kvp chunk sums -------------
__global__ void build_eff(const float* __restrict__ kvp,
                          float* __restrict__ keff, float* __restrict__ veff)
{
    int idx = blockIdx.x * blockDim.x + threadIdx.x;   // 0..512*64-1
    if (idx >= WCHUNK * DHEAD) return;
    int y = idx >> 6;
    int d = idx & 63;

    float ks = 0.f, vs = 0.f, kf = 0.f, vf = 0.f, kl = 0.f, vl = 0.f;
#pragma unroll
    for (int c = 0; c < NCHUNK; c++) {
        const float* row = kvp + (size_t)((c << 9) + y) * (2 * DHEAD);
        float kx = row[d];
        float vx = row[DHEAD + d];
        if (c == 0)          { kf = kx; vf = vx; }
        if (c == NCHUNK - 1) { kl = kx; vl = vx; }
        ks += kx; vs += vx;
    }
    // e=0: all chunks except last; e=1: all; e=2: all except first
    keff[(0 * WCHUNK + y) * DHEAD + d] = ks - kl;
    keff[(1 * WCHUNK + y) * DHEAD + d] = ks;
    keff[(2 * WCHUNK + y) * DHEAD + d] = ks - kf;
    veff[(0 * WCHUNK + y) * DHEAD + d] = vs - vl;
    veff[(1 * WCHUNK + y) * DHEAD + d] = vs;
    veff[(2 * WCHUNK + y) * DHEAD + d] = vs - vf;
}

// -------------------- fused attention: softmax(Q K^T) V -------------------
// Q:[65536,64] (== qp reinterpreted), K,V:[1536,64] shared by all queries.
// Block: 256 threads, 64 query rows, key tiles of 64. Online softmax.
// Smem: Qs | KPs (K tile reused as P tile) | Vs, stride 68 floats.
#define AT_STRIDE 68
#define AT_SMEM_BYTES (3 * 64 * AT_STRIDE * 4)

__global__ __launch_bounds__(256) void attn_kernel(
    const float* __restrict__ Q, const float* __restrict__ Keff,
    const float* __restrict__ Veff, float* __restrict__ O)
{
    extern __shared__ float sm[];
    float* Qs  = sm;                       // [64][68]
    float* KPs = sm + 64 * AT_STRIDE;      // [64][68]  K tile, then P tile
    float* Vs  = sm + 2 * 64 * AT_STRIDE;  // [64][68]

    const int tid = threadIdx.x;
    const int ty = tid >> 4;     // 0..15 -> query rows ty*4..+3
    const int tx = tid & 15;     // 0..15 -> key cols / out dims tx*4..+3
    const int qbase = blockIdx.x * 64;

    // load Q tile (64x64)
    for (int i = tid; i < 64 * 16; i += 256) {
        int r = i >> 4, c4 = (i & 15) * 4;
        float4 v = *(const float4*)&Q[(size_t)(qbase + r) * 64 + c4];
        *(float4*)&Qs[r * AT_STRIDE + c4] = v;
    }

    float m[4], l[4], o[4][4];
#pragma unroll
    for (int i = 0; i < 4; i++) {
        m[i] = -1e30f; l[i] = 0.f;
#pragma unroll
        for (int j = 0; j < 4; j++) o[i][j] = 0.f;
    }

    for (int kt = 0; kt < NKEY / 64; ++kt) {
        __syncthreads();   // previous PV stage done reading KPs/Vs
        const int kbase = kt * 64;
        for (int i = tid; i < 64 * 16; i += 256) {
            int r = i >> 4, c4 = (i & 15) * 4;
            *(float4*)&KPs[r * AT_STRIDE + c4] =
                *(const float4*)&Keff[(size_t)(kbase + r) * 64 + c4];
            *(float4*)&Vs[r * AT_STRIDE + c4] =
                *(const float4*)&Veff[(size_t)(kbase + r) * 64 + c4];
        }
        __syncthreads();

        // S = Q K^T, 4x4 microtile
        float s[4][4];
#pragma unroll
        for (int i = 0; i < 4; i++)
#pragma unroll
            for (int j = 0; j < 4; j++) s[i][j] = 0.f;

#pragma unroll
        for (int d0 = 0; d0 < 64; d0 += 4) {
            float4 a[4], b[4];
#pragma unroll
            for (int i = 0; i < 4; i++)
                a[i] = *(const float4*)&Qs[(ty * 4 + i) * AT_STRIDE + d0];
#pragma unroll
            for (int j = 0; j < 4; j++)
                b[j] = *(const float4*)&KPs[(tx * 4 + j) * AT_STRIDE + d0];
#pragma unroll
            for (int i = 0; i < 4; i++)
#pragma unroll
                for (int j = 0; j < 4; j++)
                    s[i][j] += a[i].x * b[j].x + a[i].y * b[j].y +
                               a[i].z * b[j].z + a[i].w * b[j].w;
        }

        // online softmax (m/l replicated across the 16 lanes sharing rows)
        float mnew[4], corr[4];
#pragma unroll
        for (int i = 0; i < 4; i++) {
            float rm = s[i][0];
            rm = fmaxf(rm, s[i][1]); rm = fmaxf(rm, s[i][2]); rm = fmaxf(rm, s[i][3]);
#pragma unroll
            for (int sh = 1; sh < 16; sh <<= 1)
                rm = fmaxf(rm, __shfl_xor_sync(0xffffffffu, rm, sh));
            mnew[i] = fmaxf(m[i], rm);
            corr[i] = __expf(m[i] - mnew[i]);
            m[i] = mnew[i];
        }
        float p[4][4];
#pragma unroll
        for (int i = 0; i < 4; i++) {
            float rs = 0.f;
#pragma unroll
            for (int j = 0; j < 4; j++) {
                p[i][j] = __expf(s[i][j] - mnew[i]);
                rs += p[i][j];
            }
#pragma unroll
            for (int sh = 1; sh < 16; sh <<= 1)
                rs += __shfl_xor_sync(0xffffffffu, rs, sh);
            l[i] = l[i] * corr[i] + rs;
#pragma unroll
            for (int j = 0; j < 4; j++) o[i][j] *= corr[i];
        }

        __syncthreads();   // done reading K tile -> reuse as P tile
#pragma unroll
        for (int i = 0; i < 4; i++)
            *(float4*)&KPs[(ty * 4 + i) * AT_STRIDE + tx * 4] = *(float4*)p[i];
        __syncthreads();

        // O += P V
#pragma unroll 4
        for (int c = 0; c < 64; ++c) {
            float4 vv = *(const float4*)&Vs[c * AT_STRIDE + tx * 4];
#pragma unroll
            for (int i = 0; i < 4; i++) {
                float pv = KPs[(ty * 4 + i) * AT_STRIDE + c];
                o[i][0] += pv * vv.x; o[i][1] += pv * vv.y;
                o[i][2] += pv * vv.z; o[i][3] += pv * vv.w;
            }
        }
    }

#pragma unroll
    for (int i = 0; i < 4; i++) {
        float inv = 1.f / l[i];
        float4 v;
        v.x = o[i][0] * inv; v.y = o[i][1] * inv;
        v.z = o[i][2] * inv; v.w = o[i][3] * inv;
        *(float4*)&O[(size_t)(qbase + ty * 4 + i) * 64 + tx * 4] = v;
    }
}

// -------------------- launch --------------------
extern "C" void kernel_launch(void* const* d_in, const int* in_sizes, int n_in,
                              void* d_out, int out_size)
{
    const float* q   = (const float*)d_in[0];
    const float* kv  = (const float*)d_in[1];
    const float* Wq  = (const float*)d_in[2];
    const float* Wkv = (const float*)d_in[3];
    const float* Wc  = (const float*)d_in[4];
    float* out = (float*)d_out;

    float *qp, *kvp, *keff, *veff, *ctx;
    cudaGetSymbolAddress((void**)&qp,   g_qp);
    cudaGetSymbolAddress((void**)&kvp,  g_kvp);
    cudaGetSymbolAddress((void**)&keff, g_keff);
    cudaGetSymbolAddress((void**)&veff, g_veff);
    cudaGetSymbolAddress((void**)&ctx,  g_ctx);

    cudaFuncSetAttribute(attn_kernel,
                         cudaFuncAttributeMaxDynamicSharedMemorySize,
                         AT_SMEM_BYTES);

    // kvp = kv @ Wkv  (4096 x 128 x 1024)
    sgemm128<<<dim3(1, 32), 256>>>(kv, Wkv, kvp, L_TOK, 2 * DHEAD, DMODEL, 1.0f);
    // K_eff / V_eff chunk sums
    build_eff<<<(WCHUNK * DHEAD + 255) / 256, 256>>>(kvp, keff, veff);
    // qp = (q @ Wq) / sqrt(dh)  (4096 x 1024 x 1024)
    sgemm128<<<dim3(8, 32), 256>>>(q, Wq, qp, L_TOK, DMODEL, DMODEL, 0.125f);
    // attention: Q[65536,64] vs shared K/V[1536,64]
    attn_kernel<<<NQROW / 64, 256, AT_SMEM_BYTES>>>(qp, keff, veff, ctx);
    // out = ctx @ Wc  (4096 x 1024 x 1024)
    sgemm128<<<dim3(8, 32), 256>>>(ctx, Wc, out, L_TOK, DMODEL, DMODEL, 1.0f);
}

// round 3
// speedup vs baseline: 1.0019x; 1.0019x over previous
#include <cuda_runtime.h>
#include <cuda_bf16.h>
#include <math.h>

// Problem constants (B=1, L=4096, DM=1024, NH=16, DH=64, w=512, C=8)
#define L_TOK   4096
#define DMODEL  1024
#define NHEAD   16
#define DHEAD   64
#define WCHUNK  512
#define NCHUNK  8
#define NKEY    (3 * WCHUNK)        // 1536 effective keys
#define NQROW   (L_TOK * NHEAD)     // 65536 query rows of dim 64

// -------------------- scratch (no cudaMalloc allowed) --------------------
__device__ float g_qp [L_TOK * DMODEL];       // 16 MB
__device__ float g_kvp[L_TOK * 2 * DHEAD];    // 2 MB
__device__ float g_keff[NKEY * DHEAD];        // 384 KB
__device__ float g_veff[NKEY * DHEAD];        // 384 KB
__device__ float g_ctx[L_TOK * DMODEL];       // 16 MB

// -------------------- generic tiled SGEMM: C = alpha * A(MxK) * B(KxN) ----
// BM=BN=128, BK=8, 256 threads, 8x8 microtile. M,N,K multiples of tiles.
__global__ __launch_bounds__(256) void sgemm128(
    const float* __restrict__ A, const float* __restrict__ B,
    float* __restrict__ C, int M, int N, int K, float alpha)
{
    __shared__ float As[8][128];
    __shared__ float Bs[8][128];

    const int tid = threadIdx.x;
    const int bm = blockIdx.y * 128;
    const int bn = blockIdx.x * 128;
    const int tr = tid >> 4;          // 0..15
    const int tc = tid & 15;          // 0..15

    // A loader: thread -> (row = tid/2, kcol = (tid&1)*4), float4 along K
    const int arow = tid >> 1;
    const int acol = (tid & 1) * 4;
    // B loader: thread -> (krow = tid/32, col = (tid&31)*4), float4 along N
    const int brow = tid >> 5;
    const int bcol = (tid & 31) * 4;

    const float* Aptr = A + (size_t)(bm + arow) * K + acol;
    const float* Bptr = B + (size_t)brow * N + bn + bcol;

    float acc[8][8];
#pragma unroll
    for (int i = 0; i < 8; i++)
#pragma unroll
        for (int j = 0; j < 8; j++) acc[i][j] = 0.f;

    for (int k0 = 0; k0 < K; k0 += 8) {
        float4 av = *(const float4*)(Aptr + k0);
        float4 bv = *(const float4*)(Bptr + (size_t)k0 * N);
        __syncthreads();                 // previous tile's compute done
        As[acol + 0][arow] = av.x;
        As[acol + 1][arow] = av.y;
        As[acol + 2][arow] = av.z;
        As[acol + 3][arow] = av.w;
        *(float4*)&Bs[brow][bcol] = bv;
        __syncthreads();

#pragma unroll
        for (int kk = 0; kk < 8; ++kk) {
            float a[8], b[8];
            *(float4*)(a)     = *(const float4*)&As[kk][tr * 8];
            *(float4*)(a + 4) = *(const float4*)&As[kk][tr * 8 + 4];
            *(float4*)(b)     = *(const float4*)&Bs[kk][tc * 8];
            *(float4*)(b + 4) = *(const float4*)&Bs[kk][tc * 8 + 4];
#pragma unroll
            for (int i = 0; i < 8; i++)
#pragma unroll
                for (int j = 0; j < 8; j++)
                    acc[i][j] += a[i] * b[j];
        }
    }

#pragma unroll
    for (int i = 0; i < 8; i++) {
        float* crow = C + (size_t)(bm + tr * 8 + i) * N + bn + tc * 8;
#pragma unroll
        for (int j4 = 0; j4 < 2; j4++) {
            float4 v;
            v.x = alpha * acc[i][j4 * 4 + 0];
            v.y = alpha * acc[i][j4 * 4 + 1];
            v.z = alpha * acc[i][j4 * 4 + 2];
            v.w = alpha * acc[i][j4 * 4 + 3];
            *(float4*)(crow + j4 * 4) = v;
        }
    }
}

// -------------------- build K_eff / V_eff from kvp chunk sums -------------
__global__ void build_eff(const float* __restrict__ kvp,
                          float* __restrict__ keff, float* __restrict__ veff)
{
    int idx = blockIdx.x * blockDim.x + threadIdx.x;   // 0..512*64-1
    if (idx >= WCHUNK * DHEAD) return;
    int y = idx >> 6;
    int d = idx & 63;

    float ks = 0.f, vs = 0.f, kf = 0.f, vf = 0.f, kl = 0.f, vl = 0.f;
#pragma unroll
    for (int c = 0; c < NCHUNK; c++) {
        const float* row = kvp + (size_t)((c << 9) + y) * (2 * DHEAD);
        float kx = row[d];
        float vx = row[DHEAD + d];
        if (c == 0)          { kf = kx; vf = vx; }
        if (c == NCHUNK - 1) { kl = kx; vl = vx; }
        ks += kx; vs += vx;
    }
    // e=0: all chunks except last; e=1: all; e=2: all except first
    keff[(0 * WCHUNK + y) * DHEAD + d] = ks - kl;
    keff[(1 * WCHUNK + y) * DHEAD + d] = ks;
    keff[(2 * WCHUNK + y) * DHEAD + d] = ks - kf;
    veff[(0 * WCHUNK + y) * DHEAD + d] = vs - vl;
    veff[(1 * WCHUNK + y) * DHEAD + d] = vs;
    veff[(2 * WCHUNK + y) * DHEAD + d] = vs - vf;
}

// -------------------- fused attention: softmax(Q K^T) V -------------------
// Q:[65536,64] (== qp reinterpreted), K,V:[1536,64] shared by all queries.
// Block: 256 threads, 64 query rows, key tiles of 64. Online softmax.
// Smem: Qs | KPs (K tile reused as P tile) | Vs, stride 68 floats.
#define AT_STRIDE 68
#define AT_SMEM_BYTES (3 * 64 * AT_STRIDE * 4)

__global__ __launch_bounds__(256) void attn_kernel(
    const float* __restrict__ Q, const float* __restrict__ Keff,
    const float* __restrict__ Veff, float* __restrict__ O)
{
    extern __shared__ float sm[];
    float* Qs  = sm;                       // [64][68]
    float* KPs = sm + 64 * AT_STRIDE;      // [64][68]  K tile, then P tile
    float* Vs  = sm + 2 * 64 * AT_STRIDE;  // [64][68]

    const int tid = threadIdx.x;
    const int ty = tid >> 4;     // 0..15 -> query rows ty*4..+3
    const int tx = tid & 15;     // 0..15 -> key cols / out dims tx*4..+3
    const int qbase = blockIdx.x * 64;

    // load Q tile (64x64)
    for (int i = tid; i < 64 * 16; i += 256) {
        int r = i >> 4, c4 = (i & 15) * 4;
        float4 v = *(const float4*)&Q[(size_t)(qbase + r) * 64 + c4];
        *(float4*)&Qs[r * AT_STRIDE + c4] = v;
    }

    float m[4], l[4], o[4][4];
#pragma unroll
    for (int i = 0; i < 4; i++) {
        m[i] = -1e30f; l[i] = 0.f;
#pragma unroll
        for (int j = 0; j < 4; j++) o[i][j] = 0.f;
    }

    for (int kt = 0; kt < NKEY / 64; ++kt) {
        __syncthreads();   // previous PV stage done reading KPs/Vs
        const int kbase = kt * 64;
        for (int i = tid; i < 64 * 16; i += 256) {
            int r = i >> 4, c4 = (i & 15) * 4;
            *(float4*)&KPs[r * AT_STRIDE + c4] =
                *(const float4*)&Keff[(size_t)(kbase + r) * 64 + c4];
            *(float4*)&Vs[r * AT_STRIDE + c4] =
                *(const float4*)&Veff[(size_t)(kbase + r) * 64 + c4];
        }
        __syncthreads();

        // S = Q K^T, 4x4 microtile
        float s[4][4];
#pragma unroll
        for (int i = 0; i < 4; i++)
#pragma unroll
            for (int j = 0; j < 4; j++) s[i][j] = 0.f;

#pragma unroll
        for (int d0 = 0; d0 < 64; d0 += 4) {
            float4 a[4], b[4];
#pragma unroll
            for (int i = 0; i < 4; i++)
                a[i] = *(const float4*)&Qs[(ty * 4 + i) * AT_STRIDE + d0];
#pragma unroll
            for (int j = 0; j < 4; j++)
                b[j] = *(const float4*)&KPs[(tx * 4 + j) * AT_STRIDE + d0];
#pragma unroll
            for (int i = 0; i < 4; i++)
#pragma unroll
                for (int j = 0; j < 4; j++)
                    s[i][j] += a[i].x * b[j].x + a[i].y * b[j].y +
                               a[i].z * b[j].z + a[i].w * b[j].w;
        }

        // online softmax (m/l replicated across the 16 lanes sharing rows)
        float mnew[4], corr[4];
#pragma unroll
        for (int i = 0; i < 4; i++) {
            float rm = s[i][0];
            rm = fmaxf(rm, s[i][1]); rm = fmaxf(rm, s[i][2]); rm = fmaxf(rm, s[i][3]);
#pragma unroll
            for (int sh = 1; sh < 16; sh <<= 1)
                rm = fmaxf(rm, __shfl_xor_sync(0xffffffffu, rm, sh));
            mnew[i] = fmaxf(m[i], rm);
            corr[i] = __expf(m[i] - mnew[i]);
            m[i] = mnew[i];
        }
        float p[4][4];
#pragma unroll
        for (int i = 0; i < 4; i++) {
            float rs = 0.f;
#pragma unroll
            for (int j = 0; j < 4; j++) {
                p[i][j] = __expf(s[i][j] - mnew[i]);
                rs += p[i][j];
            }
#pragma unroll
            for (int sh = 1; sh < 16; sh <<= 1)
                rs += __shfl_xor_sync(0xffffffffu, rs, sh);
            l[i] = l[i] * corr[i] + rs;
#pragma unroll
            for (int j = 0; j < 4; j++) o[i][j] *= corr[i];
        }

        __syncthreads();   // done reading K tile -> reuse as P tile
#pragma unroll
        for (int i = 0; i < 4; i++)
            *(float4*)&KPs[(ty * 4 + i) * AT_STRIDE + tx * 4] = *(float4*)p[i];
        __syncthreads();

        // O += P V
#pragma unroll 4
        for (int c = 0; c < 64; ++c) {
            float4 vv = *(const float4*)&Vs[c * AT_STRIDE + tx * 4];
#pragma unroll
            for (int i = 0; i < 4; i++) {
                float pv = KPs[(ty * 4 + i) * AT_STRIDE + c];
                o[i][0] += pv * vv.x; o[i][1] += pv * vv.y;
                o[i][2] += pv * vv.z; o[i][3] += pv * vv.w;
            }
        }
    }

#pragma unroll
    for (int i = 0; i < 4; i++) {
        float inv = 1.f / l[i];
        float4 v;
        v.x = o[i][0] * inv; v.y = o[i][1] * inv;
        v.z = o[i][2] * inv; v.w = o[i][3] * inv;
        *(float4*)&O[(size_t)(qbase + ty * 4 + i) * 64 + tx * 4] = v;
    }
}

// -------------------- launch --------------------
extern "C" void kernel_launch(void* const* d_in, const int* in_sizes, int n_in,
                              void* d_out, int out_size)
{
    const float* q   = (const float*)d_in[0];
    const float* kv  = (const float*)d_in[1];
    const float* Wq  = (const float*)d_in[2];
    const float* Wkv = (const float*)d_in[3];
    const float* Wc  = (const float*)d_in[4];
    float* out = (float*)d_out;

    float *qp, *kvp, *keff, *veff, *ctx;
    cudaGetSymbolAddress((void**)&qp,   g_qp);
    cudaGetSymbolAddress((void**)&kvp,  g_kvp);
    cudaGetSymbolAddress((void**)&keff, g_keff);
    cudaGetSymbolAddress((void**)&veff, g_veff);
    cudaGetSymbolAddress((void**)&ctx,  g_ctx);

    cudaFuncSetAttribute(attn_kernel,
                         cudaFuncAttributeMaxDynamicSharedMemorySize,
                         AT_SMEM_BYTES);

    // kvp = kv @ Wkv  (4096 x 128 x 1024)
    sgemm128<<<dim3(1, 32), 256>>>(kv, Wkv, kvp, L_TOK, 2 * DHEAD, DMODEL, 1.0f);
    // K_eff / V_eff chunk sums
    build_eff<<<(WCHUNK * DHEAD + 255) / 256, 256>>>(kvp, keff, veff);
    // qp = (q @ Wq) / sqrt(dh)  (4096 x 1024 x 1024)
    sgemm128<<<dim3(8, 32), 256>>>(q, Wq, qp, L_TOK, DMODEL, DMODEL, 0.125f);
    // attention: Q[65536,64] vs shared K/V[1536,64]
    attn_kernel<<<NQROW / 64, 256, AT_SMEM_BYTES>>>(qp, keff, veff, ctx);
    // out = ctx @ Wc  (4096 x 1024 x 1024)
    sgemm128<<<dim3(8, 32), 256>>>(ctx, Wc, out, L_TOK, DMODEL, DMODEL, 1.0f);
}